// round 9
// baseline (speedup 1.0000x reference)
#include <cuda_runtime.h>
#include <cuda_bf16.h>
#include <cstdint>

#define NLEV   14
#define TMASK  524287u        // (1<<19)-1
#define PRIME1 2654435761u
#define PRIME2 805459861u
#define MAXN   500000
#define NPAD   64             // padded bf16 input row per point (36 -> 64)
#define XPITCH 72             // smem row pitch in bf16 (144B -> conflict-free)

// ---- device scratch (bss, not allocations) ----
__device__ __align__(16) __nv_bfloat16 g_xb[(size_t)MAXN * NPAD];  // 64 MB
__device__ __align__(16) uint32_t g_bfrag[4096];  // mma B-fragments, 2 layers

__device__ __constant__ float c_res[NLEV] =
    {16.f, 21.f, 27.f, 36.f, 48.f, 64.f, 84.f, 111.f,
     147.f, 194.f, 256.f, 339.f, 447.f, 590.f};

// ---------------------------------------------------------------------------
// helpers (baseline PTX only — must assemble for plain sm_103)
// ---------------------------------------------------------------------------
__device__ __forceinline__ float tanh_hw(float x) {
    float y; asm("tanh.approx.f32 %0, %1;" : "=f"(y) : "f"(x)); return y;
}
// packed bf16x2: lo argument lands in low 16 bits
__device__ __forceinline__ uint32_t cvt_bf2(float lo, float hi) {
    uint32_t r;
    asm("cvt.rn.bf16x2.f32 %0, %1, %2;" : "=r"(r) : "f"(hi), "f"(lo));
    return r;
}
__device__ __forceinline__ void mma16816(float& d0, float& d1, float& d2, float& d3,
                                         uint32_t a0, uint32_t a1, uint32_t a2, uint32_t a3,
                                         uint32_t b0, uint32_t b1) {
    asm volatile(
        "mma.sync.aligned.m16n8k16.row.col.f32.bf16.bf16.f32 "
        "{%0,%1,%2,%3}, {%4,%5,%6,%7}, {%8,%9}, {%0,%1,%2,%3};"
        : "+f"(d0), "+f"(d1), "+f"(d2), "+f"(d3)
        : "r"(a0), "r"(a1), "r"(a2), "r"(a3), "r"(b0), "r"(b1));
}

// ===========================================================================
// Kernel 0: pack W1 (zero-padded k>=36) and W2 into per-lane B-fragment
// layout for mma.m16n8k16: for (L, nt, ks, lane):
//   reg0 = {W[k0][n], W[k0+1][n]},  reg1 = {W[k0+8][n], W[k0+9][n]}
// with k0 = ks*16 + (lane%4)*2, n = nt*8 + lane/4.  W indexed [k][n] natural.
// ===========================================================================
__global__ void convert_weights(const float* __restrict__ W1,
                                const float* __restrict__ W2)
{
    int t = blockIdx.x * blockDim.x + threadIdx.x;
    if (t >= 2048) return;
    int lane = t & 31;
    int ks   = (t >> 5) & 3;
    int nt   = (t >> 7) & 7;
    int L    = (t >> 10);
    int g = lane >> 2, tig = lane & 3;
    int nn = nt * 8 + g;
    int k0 = ks * 16 + tig * 2;

    const float* Wm = L ? W2 : W1;
    float w00 = (L == 0 && k0     >= 36) ? 0.f : Wm[(k0)     * 64 + nn];
    float w01 = (L == 0 && k0 + 1 >= 36) ? 0.f : Wm[(k0 + 1) * 64 + nn];
    float w10 = (L == 0 && k0 + 8 >= 36) ? 0.f : Wm[(k0 + 8) * 64 + nn];
    float w11 = (L == 0 && k0 + 9 >= 36) ? 0.f : Wm[(k0 + 9) * 64 + nn];

    g_bfrag[t * 2 + 0] = cvt_bf2(w00, w01);
    g_bfrag[t * 2 + 1] = cvt_bf2(w10, w11);
}

// ===========================================================================
// Kernel 1: hash-grid encode -> bf16 padded rows [n, 64] (feats|e|zeros)
// ===========================================================================
__global__ void __launch_bounds__(256)
encode_kernel(const float* __restrict__ x,
              const float* __restrict__ e,
              const float* __restrict__ tables,
              const float* __restrict__ bbox,
              int n)
{
    int p = blockIdx.x * blockDim.x + threadIdx.x;
    if (p >= n) return;

    float lo0 = __ldg(bbox + 0), lo1 = __ldg(bbox + 1), lo2 = __ldg(bbox + 2);
    float hi0 = __ldg(bbox + 3), hi1 = __ldg(bbox + 4), hi2 = __ldg(bbox + 5);

    float xv0 = __ldg(x + (size_t)p * 3 + 0);
    float xv1 = __ldg(x + (size_t)p * 3 + 1);
    float xv2 = __ldg(x + (size_t)p * 3 + 2);

    float xn0 = (xv0 - lo0) / (hi0 - lo0);
    float xn1 = (xv1 - lo1) / (hi1 - lo1);
    float xn2 = (xv2 - lo2) / (hi2 - lo2);

    float f[2 * NLEV];

#pragma unroll
    for (int l = 0; l < NLEV; l++) {
        float r  = c_res[l];
        float p0 = xn0 * r, p1v = xn1 * r, p2v = xn2 * r;
        float b0 = floorf(p0), b1 = floorf(p1v), b2 = floorf(p2v);
        float fr0 = p0 - b0, fr1 = p1v - b1, fr2 = p2v - b2;

        float w0 = fr0 * fr0 * (3.0f - 2.0f * fr0);
        float w1 = fr1 * fr1 * (3.0f - 2.0f * fr1);
        float w2 = fr2 * fr2 * (3.0f - 2.0f * fr2);
        float u0 = 1.0f - w0, u1 = 1.0f - w1, u2 = 1.0f - w2;

        unsigned c0 = (unsigned)b0, c1 = (unsigned)b1, c2 = (unsigned)b2;
        unsigned hx0 = c0,            hx1 = c0 + 1u;
        unsigned hy0 = c1 * PRIME1,   hy1 = hy0 + PRIME1;
        unsigned hz0 = c2 * PRIME2,   hz1 = hz0 + PRIME2;

        const float2* tl = reinterpret_cast<const float2*>(tables) + ((size_t)l << 19);

        unsigned i000 = (hx0 ^ hy0 ^ hz0) & TMASK;
        unsigned i001 = (hx0 ^ hy0 ^ hz1) & TMASK;
        unsigned i010 = (hx0 ^ hy1 ^ hz0) & TMASK;
        unsigned i011 = (hx0 ^ hy1 ^ hz1) & TMASK;
        unsigned i100 = (hx1 ^ hy0 ^ hz0) & TMASK;
        unsigned i101 = (hx1 ^ hy0 ^ hz1) & TMASK;
        unsigned i110 = (hx1 ^ hy1 ^ hz0) & TMASK;
        unsigned i111 = (hx1 ^ hy1 ^ hz1) & TMASK;

        float2 t000 = __ldg(tl + i000);
        float2 t001 = __ldg(tl + i001);
        float2 t010 = __ldg(tl + i010);
        float2 t011 = __ldg(tl + i011);
        float2 t100 = __ldg(tl + i100);
        float2 t101 = __ldg(tl + i101);
        float2 t110 = __ldg(tl + i110);
        float2 t111 = __ldg(tl + i111);

        float w00 = u0 * u1, w01 = u0 * w1, w10 = w0 * u1, w11 = w0 * w1;
        float w000 = w00 * u2, w001 = w00 * w2;
        float w010 = w01 * u2, w011 = w01 * w2;
        float w100 = w10 * u2, w101 = w10 * w2;
        float w110 = w11 * u2, w111 = w11 * w2;

        float a0 = w000 * t000.x; float a1 = w000 * t000.y;
        a0 = fmaf(w001, t001.x, a0); a1 = fmaf(w001, t001.y, a1);
        a0 = fmaf(w010, t010.x, a0); a1 = fmaf(w010, t010.y, a1);
        a0 = fmaf(w011, t011.x, a0); a1 = fmaf(w011, t011.y, a1);
        a0 = fmaf(w100, t100.x, a0); a1 = fmaf(w100, t100.y, a1);
        a0 = fmaf(w101, t101.x, a0); a1 = fmaf(w101, t101.y, a1);
        a0 = fmaf(w110, t110.x, a0); a1 = fmaf(w110, t110.y, a1);
        a0 = fmaf(w111, t111.x, a0); a1 = fmaf(w111, t111.y, a1);

        f[2 * l]     = a0;
        f[2 * l + 1] = a1;
    }

    // pack row: 14 feat-pairs, 4 e-pairs, 14 zero-pairs -> 32 u32 (64 bf16)
    uint32_t pk[32];
#pragma unroll
    for (int i = 0; i < 14; i++) pk[i] = cvt_bf2(f[2 * i], f[2 * i + 1]);
    {
        const float4* ep = reinterpret_cast<const float4*>(e + (size_t)p * 8);
        float4 v0 = ep[0], v1 = ep[1];
        pk[14] = cvt_bf2(v0.x, v0.y);
        pk[15] = cvt_bf2(v0.z, v0.w);
        pk[16] = cvt_bf2(v1.x, v1.y);
        pk[17] = cvt_bf2(v1.z, v1.w);
    }
#pragma unroll
    for (int i = 18; i < 32; i++) pk[i] = 0u;

    uint4* o = reinterpret_cast<uint4*>(g_xb + (size_t)p * NPAD);
#pragma unroll
    for (int q = 0; q < 8; q++)
        o[q] = make_uint4(pk[4 * q], pk[4 * q + 1], pk[4 * q + 2], pk[4 * q + 3]);
}

// ===========================================================================
// Kernel 2: warp-MMA MLP. 128 threads = 4 warps; each warp owns 32 points.
// Layers 1&2: 2 m-tiles x 8 n-tiles x 4 k-steps of mma.m16n8k16 bf16.
// Biases folded into accumulator init. h written back over the X smem tile.
// Layer 3 (64->3) from layer-2 D fragments + shfl reduce. Residual+rescale.
// ===========================================================================
__global__ void __launch_bounds__(128)
mlp_mma_kernel(const float* __restrict__ x,
               const float* __restrict__ b1, const float* __restrict__ b2,
               const float* __restrict__ W3, const float* __restrict__ b3,
               const float* __restrict__ bbox,
               float* __restrict__ out,
               int n)
{
    __shared__ uint32_t sBf[4096];                        // 16 KB B-fragments
    __shared__ __align__(16) __nv_bfloat16 sX[4][32 * XPITCH];  // 18.4 KB
    __shared__ float sb1[64], sb2[64], sW3v[192], sb3[3];

    const int tid  = threadIdx.x;
    const int w    = tid >> 5;
    const int lane = tid & 31;
    const int g    = lane >> 2;
    const int tig  = lane & 3;

    for (int t = tid; t < 4096; t += 128) sBf[t] = g_bfrag[t];
    if (tid < 64) { sb1[tid] = b1[tid]; sb2[tid] = b2[tid]; }
    if (tid < 96) { sW3v[tid] = W3[tid]; sW3v[96 + tid] = W3[96 + tid]; }
    if (tid < 3)  sb3[tid] = b3[tid];

    // load this warp's 32 X rows into padded smem (lane <-> row)
    const int pbase = blockIdx.x * 128 + w * 32;
    {
        int pr = pbase + lane;
        int pl = (pr < n) ? pr : (n - 1);
        const uint4* src = reinterpret_cast<const uint4*>(g_xb + (size_t)pl * NPAD);
        __nv_bfloat16* dst = &sX[w][lane * XPITCH];
#pragma unroll
        for (int c = 0; c < 8; c++)
            *reinterpret_cast<uint4*>(dst + c * 8) = src[c];
    }
    __syncthreads();

    __nv_bfloat16* Xw = &sX[w][0];
    float d[2][8][4];

    // ================= Layer 1 =================
#pragma unroll
    for (int nt = 0; nt < 8; nt++) {
        float bl = sb1[nt * 8 + tig * 2], bh = sb1[nt * 8 + tig * 2 + 1];
#pragma unroll
        for (int mt = 0; mt < 2; mt++) {
            d[mt][nt][0] = bl; d[mt][nt][1] = bh;
            d[mt][nt][2] = bl; d[mt][nt][3] = bh;
        }
    }
#pragma unroll
    for (int ks = 0; ks < 4; ks++) {
        uint32_t A[2][4];
#pragma unroll
        for (int mt = 0; mt < 2; mt++) {
            int r0 = mt * 16 + g, r1 = r0 + 8;
            int kc = ks * 16 + tig * 2;
            A[mt][0] = *reinterpret_cast<const uint32_t*>(&Xw[r0 * XPITCH + kc]);
            A[mt][1] = *reinterpret_cast<const uint32_t*>(&Xw[r1 * XPITCH + kc]);
            A[mt][2] = *reinterpret_cast<const uint32_t*>(&Xw[r0 * XPITCH + kc + 8]);
            A[mt][3] = *reinterpret_cast<const uint32_t*>(&Xw[r1 * XPITCH + kc + 8]);
        }
#pragma unroll
        for (int nt = 0; nt < 8; nt++) {
            uint32_t fb0 = sBf[(((0 * 8 + nt) * 4 + ks) * 32 + lane) * 2 + 0];
            uint32_t fb1 = sBf[(((0 * 8 + nt) * 4 + ks) * 32 + lane) * 2 + 1];
            mma16816(d[0][nt][0], d[0][nt][1], d[0][nt][2], d[0][nt][3],
                     A[0][0], A[0][1], A[0][2], A[0][3], fb0, fb1);
            mma16816(d[1][nt][0], d[1][nt][1], d[1][nt][2], d[1][nt][3],
                     A[1][0], A[1][1], A[1][2], A[1][3], fb0, fb1);
        }
    }
    __syncwarp();
    // epilogue 1: h = tanh(D), write back over X tile
#pragma unroll
    for (int mt = 0; mt < 2; mt++) {
#pragma unroll
        for (int nt = 0; nt < 8; nt++) {
            int r0 = mt * 16 + g, r1 = r0 + 8;
            int c0 = nt * 8 + tig * 2;
            uint32_t h01 = cvt_bf2(tanh_hw(d[mt][nt][0]), tanh_hw(d[mt][nt][1]));
            uint32_t h23 = cvt_bf2(tanh_hw(d[mt][nt][2]), tanh_hw(d[mt][nt][3]));
            *reinterpret_cast<uint32_t*>(&Xw[r0 * XPITCH + c0]) = h01;
            *reinterpret_cast<uint32_t*>(&Xw[r1 * XPITCH + c0]) = h23;
        }
    }
    __syncwarp();

    // ================= Layer 2 =================
#pragma unroll
    for (int nt = 0; nt < 8; nt++) {
        float bl = sb2[nt * 8 + tig * 2], bh = sb2[nt * 8 + tig * 2 + 1];
#pragma unroll
        for (int mt = 0; mt < 2; mt++) {
            d[mt][nt][0] = bl; d[mt][nt][1] = bh;
            d[mt][nt][2] = bl; d[mt][nt][3] = bh;
        }
    }
#pragma unroll
    for (int ks = 0; ks < 4; ks++) {
        uint32_t A[2][4];
#pragma unroll
        for (int mt = 0; mt < 2; mt++) {
            int r0 = mt * 16 + g, r1 = r0 + 8;
            int kc = ks * 16 + tig * 2;
            A[mt][0] = *reinterpret_cast<const uint32_t*>(&Xw[r0 * XPITCH + kc]);
            A[mt][1] = *reinterpret_cast<const uint32_t*>(&Xw[r1 * XPITCH + kc]);
            A[mt][2] = *reinterpret_cast<const uint32_t*>(&Xw[r0 * XPITCH + kc + 8]);
            A[mt][3] = *reinterpret_cast<const uint32_t*>(&Xw[r1 * XPITCH + kc + 8]);
        }
#pragma unroll
        for (int nt = 0; nt < 8; nt++) {
            uint32_t fb0 = sBf[(((1 * 8 + nt) * 4 + ks) * 32 + lane) * 2 + 0];
            uint32_t fb1 = sBf[(((1 * 8 + nt) * 4 + ks) * 32 + lane) * 2 + 1];
            mma16816(d[0][nt][0], d[0][nt][1], d[0][nt][2], d[0][nt][3],
                     A[0][0], A[0][1], A[0][2], A[0][3], fb0, fb1);
            mma16816(d[1][nt][0], d[1][nt][1], d[1][nt][2], d[1][nt][3],
                     A[1][0], A[1][1], A[1][2], A[1][3], fb0, fb1);
        }
    }

    // ============ epilogue 2 + layer 3 + residual + store ============
#pragma unroll
    for (int mt = 0; mt < 2; mt++) {
        float s0[3] = {0.f, 0.f, 0.f};   // row mt*16+g
        float s1[3] = {0.f, 0.f, 0.f};   // row mt*16+g+8
#pragma unroll
        for (int nt = 0; nt < 8; nt++) {
            int c0 = nt * 8 + tig * 2, c1 = c0 + 1;
            float t00 = tanh_hw(d[mt][nt][0]);
            float t01 = tanh_hw(d[mt][nt][1]);
            float t10 = tanh_hw(d[mt][nt][2]);
            float t11 = tanh_hw(d[mt][nt][3]);
#pragma unroll
            for (int k = 0; k < 3; k++) {
                float w0 = sW3v[c0 * 3 + k], w1 = sW3v[c1 * 3 + k];
                s0[k] = fmaf(t00, w0, s0[k]); s0[k] = fmaf(t01, w1, s0[k]);
                s1[k] = fmaf(t10, w0, s1[k]); s1[k] = fmaf(t11, w1, s1[k]);
            }
        }
        // reduce over the 4 lanes of the group (tig axis)
#pragma unroll
        for (int k = 0; k < 3; k++) {
            s0[k] += __shfl_xor_sync(0xffffffffu, s0[k], 1);
            s0[k] += __shfl_xor_sync(0xffffffffu, s0[k], 2);
            s1[k] += __shfl_xor_sync(0xffffffffu, s1[k], 1);
            s1[k] += __shfl_xor_sync(0xffffffffu, s1[k], 2);
        }
        if (tig == 0) {
            int p0 = pbase + mt * 16 + g;
            int p1 = p0 + 8;
#pragma unroll
            for (int k = 0; k < 3; k++) {
                float lo = __ldg(bbox + k), hi = __ldg(bbox + 3 + k);
                float scale = hi - lo;
                if (p0 < n) {
                    float xn = (__ldg(x + (size_t)p0 * 3 + k) - lo) / scale;
                    out[(size_t)p0 * 3 + k] = (s0[k] + sb3[k] + xn) * scale + lo;
                }
                if (p1 < n) {
                    float xn = (__ldg(x + (size_t)p1 * 3 + k) - lo) / scale;
                    out[(size_t)p1 * 3 + k] = (s1[k] + sb3[k] + xn) * scale + lo;
                }
            }
        }
    }
}

// ---------------------------------------------------------------------------
// kernel_launch: three launches, graph-capturable, allocation-free.
// Input order: x, e, tables, W1, b1, W2, b2, W3, b3, bounding_box
// ---------------------------------------------------------------------------
extern "C" void kernel_launch(void* const* d_in, const int* in_sizes, int n_in,
                              void* d_out, int out_size)
{
    const float* x      = (const float*)d_in[0];
    const float* e      = (const float*)d_in[1];
    const float* tables = (const float*)d_in[2];
    const float* W1     = (const float*)d_in[3];
    const float* b1     = (const float*)d_in[4];
    const float* W2     = (const float*)d_in[5];
    const float* b2     = (const float*)d_in[6];
    const float* W3     = (const float*)d_in[7];
    const float* b3     = (const float*)d_in[8];
    const float* bbox   = (const float*)d_in[9];

    int n = in_sizes[0] / 3;
    if (n > MAXN) n = MAXN;

    convert_weights<<<8, 256>>>(W1, W2);

    int eb = 256;
    encode_kernel<<<(n + eb - 1) / eb, eb>>>(x, e, tables, bbox, n);

    int blocks = (n + 127) / 128;
    mlp_mma_kernel<<<blocks, 128>>>(x, b1, b2, W3, b3, bbox, (float*)d_out, n);
}

// round 11
// speedup vs baseline: 1.8447x; 1.8447x over previous
#include <cuda_runtime.h>
#include <cuda_bf16.h>
#include <cstdint>

#define NLEV   14
#define TMASK  524287u        // (1<<19)-1
#define PRIME1 2654435761u
#define PRIME2 805459861u
#define MAXN   500000
#define XPITCH 72             // smem row pitch in bf16 (144B -> conflict-free)

// mma B-fragments for W1 (k-padded) and W2, built once per launch
__device__ __align__(16) uint32_t g_bfrag[4096];

__device__ __constant__ float c_res[NLEV] =
    {16.f, 21.f, 27.f, 36.f, 48.f, 64.f, 84.f, 111.f,
     147.f, 194.f, 256.f, 339.f, 447.f, 590.f};

// ---------------------------------------------------------------------------
// helpers (baseline PTX only — must assemble for plain sm_103)
// ---------------------------------------------------------------------------
__device__ __forceinline__ float tanh_hw(float x) {
    float y; asm("tanh.approx.f32 %0, %1;" : "=f"(y) : "f"(x)); return y;
}
// packed bf16x2: lo argument lands in low 16 bits
__device__ __forceinline__ uint32_t cvt_bf2(float lo, float hi) {
    uint32_t r;
    asm("cvt.rn.bf16x2.f32 %0, %1, %2;" : "=r"(r) : "f"(hi), "f"(lo));
    return r;
}
__device__ __forceinline__ void mma16816(float& d0, float& d1, float& d2, float& d3,
                                         uint32_t a0, uint32_t a1, uint32_t a2, uint32_t a3,
                                         uint32_t b0, uint32_t b1) {
    asm volatile(
        "mma.sync.aligned.m16n8k16.row.col.f32.bf16.bf16.f32 "
        "{%0,%1,%2,%3}, {%4,%5,%6,%7}, {%8,%9}, {%0,%1,%2,%3};"
        : "+f"(d0), "+f"(d1), "+f"(d2), "+f"(d3)
        : "r"(a0), "r"(a1), "r"(a2), "r"(a3), "r"(b0), "r"(b1));
}

// ===========================================================================
// Kernel 0: pack W1 (zero-padded k>=36) and W2 into per-lane B-fragments
// (layout verified in R8: rel_err 1.9e-12)
// ===========================================================================
__global__ void convert_weights(const float* __restrict__ W1,
                                const float* __restrict__ W2)
{
    int t = blockIdx.x * blockDim.x + threadIdx.x;
    if (t >= 2048) return;
    int lane = t & 31;
    int ks   = (t >> 5) & 3;
    int nt   = (t >> 7) & 7;
    int L    = (t >> 10);
    int g = lane >> 2, tig = lane & 3;
    int nn = nt * 8 + g;
    int k0 = ks * 16 + tig * 2;

    const float* Wm = L ? W2 : W1;
    float w00 = (L == 0 && k0     >= 36) ? 0.f : Wm[(k0)     * 64 + nn];
    float w01 = (L == 0 && k0 + 1 >= 36) ? 0.f : Wm[(k0 + 1) * 64 + nn];
    float w10 = (L == 0 && k0 + 8 >= 36) ? 0.f : Wm[(k0 + 8) * 64 + nn];
    float w11 = (L == 0 && k0 + 9 >= 36) ? 0.f : Wm[(k0 + 9) * 64 + nn];

    g_bfrag[t * 2 + 0] = cvt_bf2(w00, w01);
    g_bfrag[t * 2 + 1] = cvt_bf2(w10, w11);
}

// ===========================================================================
// Fused kernel: hash-grid encode -> smem bf16 X-tile -> warp-MMA MLP.
// One CTA = 128 threads = 128 points. No global feature scratch.
// ===========================================================================
__global__ void __launch_bounds__(128)
fused_kernel(const float* __restrict__ x,
             const float* __restrict__ e,
             const float* __restrict__ tables,
             const float* __restrict__ b1, const float* __restrict__ b2,
             const float* __restrict__ W3, const float* __restrict__ b3,
             const float* __restrict__ bbox,
             float* __restrict__ out,
             int n)
{
    __shared__ uint32_t sBf[4096];                             // 16 KB
    __shared__ __align__(16) __nv_bfloat16 sX[128 * XPITCH];   // 18.4 KB
    __shared__ float sb1[64], sb2[64], sW3v[192], sb3[3];

    const int tid  = threadIdx.x;
    const int w    = tid >> 5;
    const int lane = tid & 31;
    const int g    = lane >> 2;
    const int tig  = lane & 3;

    // ---- stage B-fragments & small params (issue loads early) ----
    for (int t = tid; t < 4096; t += 128) sBf[t] = g_bfrag[t];
    if (tid < 64) { sb1[tid] = b1[tid]; sb2[tid] = b2[tid]; }
    if (tid < 96) { sW3v[tid] = W3[tid]; sW3v[96 + tid] = W3[96 + tid]; }
    if (tid < 3)  sb3[tid] = b3[tid];

    // ================= encode phase (this thread's point) =================
    const int p  = blockIdx.x * 128 + tid;
    const int pl = (p < n) ? p : (n - 1);

    float lo0 = __ldg(bbox + 0), lo1 = __ldg(bbox + 1), lo2 = __ldg(bbox + 2);
    float hi0 = __ldg(bbox + 3), hi1 = __ldg(bbox + 4), hi2 = __ldg(bbox + 5);

    float xv0 = __ldg(x + (size_t)pl * 3 + 0);
    float xv1 = __ldg(x + (size_t)pl * 3 + 1);
    float xv2 = __ldg(x + (size_t)pl * 3 + 2);

    float xn0 = (xv0 - lo0) / (hi0 - lo0);
    float xn1 = (xv1 - lo1) / (hi1 - lo1);
    float xn2 = (xv2 - lo2) / (hi2 - lo2);

    float f[2 * NLEV];

#pragma unroll
    for (int l = 0; l < NLEV; l++) {
        float r  = c_res[l];
        float p0 = xn0 * r, p1v = xn1 * r, p2v = xn2 * r;
        float b0 = floorf(p0), b1f = floorf(p1v), b2f = floorf(p2v);
        float fr0 = p0 - b0, fr1 = p1v - b1f, fr2 = p2v - b2f;

        float w0 = fr0 * fr0 * (3.0f - 2.0f * fr0);
        float w1 = fr1 * fr1 * (3.0f - 2.0f * fr1);
        float w2 = fr2 * fr2 * (3.0f - 2.0f * fr2);
        float u0 = 1.0f - w0, u1 = 1.0f - w1, u2 = 1.0f - w2;

        unsigned c0 = (unsigned)b0, c1 = (unsigned)b1f, c2 = (unsigned)b2f;
        unsigned hx0 = c0,            hx1 = c0 + 1u;
        unsigned hy0 = c1 * PRIME1,   hy1 = hy0 + PRIME1;
        unsigned hz0 = c2 * PRIME2,   hz1 = hz0 + PRIME2;

        const float2* tl = reinterpret_cast<const float2*>(tables) + ((size_t)l << 19);

        unsigned i000 = (hx0 ^ hy0 ^ hz0) & TMASK;
        unsigned i001 = (hx0 ^ hy0 ^ hz1) & TMASK;
        unsigned i010 = (hx0 ^ hy1 ^ hz0) & TMASK;
        unsigned i011 = (hx0 ^ hy1 ^ hz1) & TMASK;
        unsigned i100 = (hx1 ^ hy0 ^ hz0) & TMASK;
        unsigned i101 = (hx1 ^ hy0 ^ hz1) & TMASK;
        unsigned i110 = (hx1 ^ hy1 ^ hz0) & TMASK;
        unsigned i111 = (hx1 ^ hy1 ^ hz1) & TMASK;

        float2 t000 = __ldg(tl + i000);
        float2 t001 = __ldg(tl + i001);
        float2 t010 = __ldg(tl + i010);
        float2 t011 = __ldg(tl + i011);
        float2 t100 = __ldg(tl + i100);
        float2 t101 = __ldg(tl + i101);
        float2 t110 = __ldg(tl + i110);
        float2 t111 = __ldg(tl + i111);

        float w00 = u0 * u1, w01 = u0 * w1, w10 = w0 * u1, w11 = w0 * w1;
        float w000 = w00 * u2, w001 = w00 * w2;
        float w010 = w01 * u2, w011 = w01 * w2;
        float w100 = w10 * u2, w101 = w10 * w2;
        float w110 = w11 * u2, w111 = w11 * w2;

        float a0 = w000 * t000.x; float a1 = w000 * t000.y;
        a0 = fmaf(w001, t001.x, a0); a1 = fmaf(w001, t001.y, a1);
        a0 = fmaf(w010, t010.x, a0); a1 = fmaf(w010, t010.y, a1);
        a0 = fmaf(w011, t011.x, a0); a1 = fmaf(w011, t011.y, a1);
        a0 = fmaf(w100, t100.x, a0); a1 = fmaf(w100, t100.y, a1);
        a0 = fmaf(w101, t101.x, a0); a1 = fmaf(w101, t101.y, a1);
        a0 = fmaf(w110, t110.x, a0); a1 = fmaf(w110, t110.y, a1);
        a0 = fmaf(w111, t111.x, a0); a1 = fmaf(w111, t111.y, a1);

        f[2 * l]     = a0;
        f[2 * l + 1] = a1;
    }

    // pack row into this thread's smem X row: 14 feat-pairs, 4 e-pairs, zeros
    {
        uint32_t pk[32];
#pragma unroll
        for (int i = 0; i < 14; i++) pk[i] = cvt_bf2(f[2 * i], f[2 * i + 1]);
        const float4* ep = reinterpret_cast<const float4*>(e + (size_t)pl * 8);
        float4 v0 = ep[0], v1 = ep[1];
        pk[14] = cvt_bf2(v0.x, v0.y);
        pk[15] = cvt_bf2(v0.z, v0.w);
        pk[16] = cvt_bf2(v1.x, v1.y);
        pk[17] = cvt_bf2(v1.z, v1.w);
#pragma unroll
        for (int i = 18; i < 32; i++) pk[i] = 0u;

        __nv_bfloat16* dst = &sX[tid * XPITCH];   // tid*144B, 16B-aligned
#pragma unroll
        for (int c = 0; c < 8; c++)
            *reinterpret_cast<uint4*>(dst + c * 8) =
                make_uint4(pk[4 * c], pk[4 * c + 1], pk[4 * c + 2], pk[4 * c + 3]);
    }
    __syncthreads();

    // ================= MMA MLP phase (verified R8 layout) =================
    __nv_bfloat16* Xw = &sX[w * 32 * XPITCH];
    const int pbase = blockIdx.x * 128 + w * 32;
    float d[2][8][4];

    // ---- Layer 1 ----
#pragma unroll
    for (int nt = 0; nt < 8; nt++) {
        float bl = sb1[nt * 8 + tig * 2], bh = sb1[nt * 8 + tig * 2 + 1];
#pragma unroll
        for (int mt = 0; mt < 2; mt++) {
            d[mt][nt][0] = bl; d[mt][nt][1] = bh;
            d[mt][nt][2] = bl; d[mt][nt][3] = bh;
        }
    }
#pragma unroll
    for (int ks = 0; ks < 4; ks++) {
        uint32_t A[2][4];
#pragma unroll
        for (int mt = 0; mt < 2; mt++) {
            int r0 = mt * 16 + g, r1 = r0 + 8;
            int kc = ks * 16 + tig * 2;
            A[mt][0] = *reinterpret_cast<const uint32_t*>(&Xw[r0 * XPITCH + kc]);
            A[mt][1] = *reinterpret_cast<const uint32_t*>(&Xw[r1 * XPITCH + kc]);
            A[mt][2] = *reinterpret_cast<const uint32_t*>(&Xw[r0 * XPITCH + kc + 8]);
            A[mt][3] = *reinterpret_cast<const uint32_t*>(&Xw[r1 * XPITCH + kc + 8]);
        }
#pragma unroll
        for (int nt = 0; nt < 8; nt++) {
            uint32_t fb0 = sBf[((nt * 4 + ks) * 32 + lane) * 2 + 0];
            uint32_t fb1 = sBf[((nt * 4 + ks) * 32 + lane) * 2 + 1];
            mma16816(d[0][nt][0], d[0][nt][1], d[0][nt][2], d[0][nt][3],
                     A[0][0], A[0][1], A[0][2], A[0][3], fb0, fb1);
            mma16816(d[1][nt][0], d[1][nt][1], d[1][nt][2], d[1][nt][3],
                     A[1][0], A[1][1], A[1][2], A[1][3], fb0, fb1);
        }
    }
    __syncwarp();
    // epilogue 1: h = tanh(D), write back over X tile
#pragma unroll
    for (int mt = 0; mt < 2; mt++) {
#pragma unroll
        for (int nt = 0; nt < 8; nt++) {
            int r0 = mt * 16 + g, r1 = r0 + 8;
            int c0 = nt * 8 + tig * 2;
            uint32_t h01 = cvt_bf2(tanh_hw(d[mt][nt][0]), tanh_hw(d[mt][nt][1]));
            uint32_t h23 = cvt_bf2(tanh_hw(d[mt][nt][2]), tanh_hw(d[mt][nt][3]));
            *reinterpret_cast<uint32_t*>(&Xw[r0 * XPITCH + c0]) = h01;
            *reinterpret_cast<uint32_t*>(&Xw[r1 * XPITCH + c0]) = h23;
        }
    }
    __syncwarp();

    // ---- Layer 2 ----
#pragma unroll
    for (int nt = 0; nt < 8; nt++) {
        float bl = sb2[nt * 8 + tig * 2], bh = sb2[nt * 8 + tig * 2 + 1];
#pragma unroll
        for (int mt = 0; mt < 2; mt++) {
            d[mt][nt][0] = bl; d[mt][nt][1] = bh;
            d[mt][nt][2] = bl; d[mt][nt][3] = bh;
        }
    }
#pragma unroll
    for (int ks = 0; ks < 4; ks++) {
        uint32_t A[2][4];
#pragma unroll
        for (int mt = 0; mt < 2; mt++) {
            int r0 = mt * 16 + g, r1 = r0 + 8;
            int kc = ks * 16 + tig * 2;
            A[mt][0] = *reinterpret_cast<const uint32_t*>(&Xw[r0 * XPITCH + kc]);
            A[mt][1] = *reinterpret_cast<const uint32_t*>(&Xw[r1 * XPITCH + kc]);
            A[mt][2] = *reinterpret_cast<const uint32_t*>(&Xw[r0 * XPITCH + kc + 8]);
            A[mt][3] = *reinterpret_cast<const uint32_t*>(&Xw[r1 * XPITCH + kc + 8]);
        }
#pragma unroll
        for (int nt = 0; nt < 8; nt++) {
            uint32_t fb0 = sBf[(((8 + nt) * 4 + ks) * 32 + lane) * 2 + 0];
            uint32_t fb1 = sBf[(((8 + nt) * 4 + ks) * 32 + lane) * 2 + 1];
            mma16816(d[0][nt][0], d[0][nt][1], d[0][nt][2], d[0][nt][3],
                     A[0][0], A[0][1], A[0][2], A[0][3], fb0, fb1);
            mma16816(d[1][nt][0], d[1][nt][1], d[1][nt][2], d[1][nt][3],
                     A[1][0], A[1][1], A[1][2], A[1][3], fb0, fb1);
        }
    }

    // ---- epilogue 2 + layer 3 + residual + store ----
#pragma unroll
    for (int mt = 0; mt < 2; mt++) {
        float s0[3] = {0.f, 0.f, 0.f};   // row mt*16+g
        float s1[3] = {0.f, 0.f, 0.f};   // row mt*16+g+8
#pragma unroll
        for (int nt = 0; nt < 8; nt++) {
            int c0 = nt * 8 + tig * 2, c1 = c0 + 1;
            float t00 = tanh_hw(d[mt][nt][0]);
            float t01 = tanh_hw(d[mt][nt][1]);
            float t10 = tanh_hw(d[mt][nt][2]);
            float t11 = tanh_hw(d[mt][nt][3]);
#pragma unroll
            for (int k = 0; k < 3; k++) {
                float w0 = sW3v[c0 * 3 + k], w1 = sW3v[c1 * 3 + k];
                s0[k] = fmaf(t00, w0, s0[k]); s0[k] = fmaf(t01, w1, s0[k]);
                s1[k] = fmaf(t10, w0, s1[k]); s1[k] = fmaf(t11, w1, s1[k]);
            }
        }
#pragma unroll
        for (int k = 0; k < 3; k++) {
            s0[k] += __shfl_xor_sync(0xffffffffu, s0[k], 1);
            s0[k] += __shfl_xor_sync(0xffffffffu, s0[k], 2);
            s1[k] += __shfl_xor_sync(0xffffffffu, s1[k], 1);
            s1[k] += __shfl_xor_sync(0xffffffffu, s1[k], 2);
        }
        if (tig == 0) {
            int p0 = pbase + mt * 16 + g;
            int p1 = p0 + 8;
#pragma unroll
            for (int k = 0; k < 3; k++) {
                float lo = __ldg(bbox + k), hi = __ldg(bbox + 3 + k);
                float scale = hi - lo;
                if (p0 < n) {
                    float xn = (__ldg(x + (size_t)p0 * 3 + k) - lo) / scale;
                    out[(size_t)p0 * 3 + k] = (s0[k] + sb3[k] + xn) * scale + lo;
                }
                if (p1 < n) {
                    float xn = (__ldg(x + (size_t)p1 * 3 + k) - lo) / scale;
                    out[(size_t)p1 * 3 + k] = (s1[k] + sb3[k] + xn) * scale + lo;
                }
            }
        }
    }
}

// ---------------------------------------------------------------------------
// kernel_launch: two launches, graph-capturable, allocation-free.
// Input order: x, e, tables, W1, b1, W2, b2, W3, b3, bounding_box
// ---------------------------------------------------------------------------
extern "C" void kernel_launch(void* const* d_in, const int* in_sizes, int n_in,
                              void* d_out, int out_size)
{
    const float* x      = (const float*)d_in[0];
    const float* e      = (const float*)d_in[1];
    const float* tables = (const float*)d_in[2];
    const float* W1     = (const float*)d_in[3];
    const float* b1     = (const float*)d_in[4];
    const float* W2     = (const float*)d_in[5];
    const float* b2     = (const float*)d_in[6];
    const float* W3     = (const float*)d_in[7];
    const float* b3     = (const float*)d_in[8];
    const float* bbox   = (const float*)d_in[9];

    int n = in_sizes[0] / 3;
    if (n > MAXN) n = MAXN;

    convert_weights<<<8, 256>>>(W1, W2);

    int blocks = (n + 127) / 128;
    fused_kernel<<<blocks, 128>>>(x, e, tables, b1, b2, W3, b3, bbox,
                                  (float*)d_out, n);
}

// round 12
// speedup vs baseline: 2.0519x; 1.1123x over previous
#include <cuda_runtime.h>
#include <cuda_bf16.h>
#include <cstdint>

#define NLEV   14
#define TMASK  524287u        // (1<<19)-1
#define PRIME1 2654435761u
#define PRIME2 805459861u
#define MAXN   500000
#define XPITCH 72             // smem row pitch in bf16 (144B -> conflict-free)

// mma B-fragments for W1 (k-padded) and W2, built once per launch.
// Read directly from global in the MMA loops: addresses are identical across
// all warps/CTAs -> coalesced + L1-resident. No smem staging (saves 16 KB).
__device__ __align__(16) uint32_t g_bfrag[4096];

__device__ __constant__ float c_res[NLEV] =
    {16.f, 21.f, 27.f, 36.f, 48.f, 64.f, 84.f, 111.f,
     147.f, 194.f, 256.f, 339.f, 447.f, 590.f};

// ---------------------------------------------------------------------------
// helpers (baseline PTX only — must assemble for plain sm_103)
// ---------------------------------------------------------------------------
__device__ __forceinline__ float tanh_hw(float x) {
    float y; asm("tanh.approx.f32 %0, %1;" : "=f"(y) : "f"(x)); return y;
}
// packed bf16x2: lo argument lands in low 16 bits
__device__ __forceinline__ uint32_t cvt_bf2(float lo, float hi) {
    uint32_t r;
    asm("cvt.rn.bf16x2.f32 %0, %1, %2;" : "=r"(r) : "f"(hi), "f"(lo));
    return r;
}
__device__ __forceinline__ void mma16816(float& d0, float& d1, float& d2, float& d3,
                                         uint32_t a0, uint32_t a1, uint32_t a2, uint32_t a3,
                                         uint32_t b0, uint32_t b1) {
    asm volatile(
        "mma.sync.aligned.m16n8k16.row.col.f32.bf16.bf16.f32 "
        "{%0,%1,%2,%3}, {%4,%5,%6,%7}, {%8,%9}, {%0,%1,%2,%3};"
        : "+f"(d0), "+f"(d1), "+f"(d2), "+f"(d3)
        : "r"(a0), "r"(a1), "r"(a2), "r"(a3), "r"(b0), "r"(b1));
}

// ===========================================================================
// Kernel 0: pack W1 (zero-padded k>=36) and W2 into per-lane B-fragments
// (layout verified: rel_err 1.9e-12)
// ===========================================================================
__global__ void convert_weights(const float* __restrict__ W1,
                                const float* __restrict__ W2)
{
    int t = blockIdx.x * blockDim.x + threadIdx.x;
    if (t >= 2048) return;
    int lane = t & 31;
    int ks   = (t >> 5) & 3;
    int nt   = (t >> 7) & 7;
    int L    = (t >> 10);
    int g = lane >> 2, tig = lane & 3;
    int nn = nt * 8 + g;
    int k0 = ks * 16 + tig * 2;

    const float* Wm = L ? W2 : W1;
    float w00 = (L == 0 && k0     >= 36) ? 0.f : Wm[(k0)     * 64 + nn];
    float w01 = (L == 0 && k0 + 1 >= 36) ? 0.f : Wm[(k0 + 1) * 64 + nn];
    float w10 = (L == 0 && k0 + 8 >= 36) ? 0.f : Wm[(k0 + 8) * 64 + nn];
    float w11 = (L == 0 && k0 + 9 >= 36) ? 0.f : Wm[(k0 + 9) * 64 + nn];

    g_bfrag[t * 2 + 0] = cvt_bf2(w00, w01);
    g_bfrag[t * 2 + 1] = cvt_bf2(w10, w11);
}

// ===========================================================================
// Fused kernel: hash-grid encode -> smem bf16 X-tile -> warp-MMA MLP.
// One CTA = 128 threads = 128 points. smem ~19.4 KB -> 11 CTAs/SM.
// ===========================================================================
__global__ void __launch_bounds__(128)
fused_kernel(const float* __restrict__ x,
             const float* __restrict__ e,
             const float* __restrict__ tables,
             const float* __restrict__ b1, const float* __restrict__ b2,
             const float* __restrict__ W3, const float* __restrict__ b3,
             const float* __restrict__ bbox,
             float* __restrict__ out,
             int n)
{
    __shared__ __align__(16) __nv_bfloat16 sX[128 * XPITCH];   // 18.4 KB
    __shared__ float sb1[64], sb2[64], sW3v[192], sb3[3];

    const int tid  = threadIdx.x;
    const int w    = tid >> 5;
    const int lane = tid & 31;
    const int g    = lane >> 2;
    const int tig  = lane & 3;

    if (tid < 64) { sb1[tid] = b1[tid]; sb2[tid] = b2[tid]; }
    if (tid < 96) { sW3v[tid] = W3[tid]; sW3v[96 + tid] = W3[96 + tid]; }
    if (tid < 3)  sb3[tid] = b3[tid];

    // ================= encode phase (this thread's point) =================
    const int p  = blockIdx.x * 128 + tid;
    const int pl = (p < n) ? p : (n - 1);

    float lo0 = __ldg(bbox + 0), lo1 = __ldg(bbox + 1), lo2 = __ldg(bbox + 2);
    float hi0 = __ldg(bbox + 3), hi1 = __ldg(bbox + 4), hi2 = __ldg(bbox + 5);

    float xv0 = __ldg(x + (size_t)pl * 3 + 0);
    float xv1 = __ldg(x + (size_t)pl * 3 + 1);
    float xv2 = __ldg(x + (size_t)pl * 3 + 2);

    float xn0 = (xv0 - lo0) / (hi0 - lo0);
    float xn1 = (xv1 - lo1) / (hi1 - lo1);
    float xn2 = (xv2 - lo2) / (hi2 - lo2);

    float f[2 * NLEV];

#pragma unroll
    for (int l = 0; l < NLEV; l++) {
        float r  = c_res[l];
        float p0 = xn0 * r, p1v = xn1 * r, p2v = xn2 * r;
        float b0 = floorf(p0), b1f = floorf(p1v), b2f = floorf(p2v);
        float fr0 = p0 - b0, fr1 = p1v - b1f, fr2 = p2v - b2f;

        float w0 = fr0 * fr0 * (3.0f - 2.0f * fr0);
        float w1 = fr1 * fr1 * (3.0f - 2.0f * fr1);
        float w2 = fr2 * fr2 * (3.0f - 2.0f * fr2);
        float u0 = 1.0f - w0, u1 = 1.0f - w1, u2 = 1.0f - w2;

        unsigned c0 = (unsigned)b0, c1 = (unsigned)b1f, c2 = (unsigned)b2f;
        unsigned hx0 = c0,            hx1 = c0 + 1u;
        unsigned hy0 = c1 * PRIME1,   hy1 = hy0 + PRIME1;
        unsigned hz0 = c2 * PRIME2,   hz1 = hz0 + PRIME2;

        const float2* tl = reinterpret_cast<const float2*>(tables) + ((size_t)l << 19);

        unsigned i000 = (hx0 ^ hy0 ^ hz0) & TMASK;
        unsigned i001 = (hx0 ^ hy0 ^ hz1) & TMASK;
        unsigned i010 = (hx0 ^ hy1 ^ hz0) & TMASK;
        unsigned i011 = (hx0 ^ hy1 ^ hz1) & TMASK;
        unsigned i100 = (hx1 ^ hy0 ^ hz0) & TMASK;
        unsigned i101 = (hx1 ^ hy0 ^ hz1) & TMASK;
        unsigned i110 = (hx1 ^ hy1 ^ hz0) & TMASK;
        unsigned i111 = (hx1 ^ hy1 ^ hz1) & TMASK;

        float2 t000 = __ldg(tl + i000);
        float2 t001 = __ldg(tl + i001);
        float2 t010 = __ldg(tl + i010);
        float2 t011 = __ldg(tl + i011);
        float2 t100 = __ldg(tl + i100);
        float2 t101 = __ldg(tl + i101);
        float2 t110 = __ldg(tl + i110);
        float2 t111 = __ldg(tl + i111);

        float w00 = u0 * u1, w01 = u0 * w1, w10 = w0 * u1, w11 = w0 * w1;
        float w000 = w00 * u2, w001 = w00 * w2;
        float w010 = w01 * u2, w011 = w01 * w2;
        float w100 = w10 * u2, w101 = w10 * w2;
        float w110 = w11 * u2, w111 = w11 * w2;

        float a0 = w000 * t000.x; float a1 = w000 * t000.y;
        a0 = fmaf(w001, t001.x, a0); a1 = fmaf(w001, t001.y, a1);
        a0 = fmaf(w010, t010.x, a0); a1 = fmaf(w010, t010.y, a1);
        a0 = fmaf(w011, t011.x, a0); a1 = fmaf(w011, t011.y, a1);
        a0 = fmaf(w100, t100.x, a0); a1 = fmaf(w100, t100.y, a1);
        a0 = fmaf(w101, t101.x, a0); a1 = fmaf(w101, t101.y, a1);
        a0 = fmaf(w110, t110.x, a0); a1 = fmaf(w110, t110.y, a1);
        a0 = fmaf(w111, t111.x, a0); a1 = fmaf(w111, t111.y, a1);

        f[2 * l]     = a0;
        f[2 * l + 1] = a1;
    }

    // pack row into this thread's smem X row: 14 feat-pairs, 4 e-pairs, zeros
    {
        uint32_t pk[32];
#pragma unroll
        for (int i = 0; i < 14; i++) pk[i] = cvt_bf2(f[2 * i], f[2 * i + 1]);
        const float4* ep = reinterpret_cast<const float4*>(e + (size_t)pl * 8);
        float4 v0 = ep[0], v1 = ep[1];
        pk[14] = cvt_bf2(v0.x, v0.y);
        pk[15] = cvt_bf2(v0.z, v0.w);
        pk[16] = cvt_bf2(v1.x, v1.y);
        pk[17] = cvt_bf2(v1.z, v1.w);
#pragma unroll
        for (int i = 18; i < 32; i++) pk[i] = 0u;

        __nv_bfloat16* dst = &sX[tid * XPITCH];   // tid*144B, 16B-aligned
#pragma unroll
        for (int c = 0; c < 8; c++)
            *reinterpret_cast<uint4*>(dst + c * 8) =
                make_uint4(pk[4 * c], pk[4 * c + 1], pk[4 * c + 2], pk[4 * c + 3]);
    }
    __syncthreads();

    // ================= MMA MLP phase (verified layout) =================
    __nv_bfloat16* Xw = &sX[w * 32 * XPITCH];
    const int pbase = blockIdx.x * 128 + w * 32;
    float d[2][8][4];

    // ---- Layer 1 ----
#pragma unroll
    for (int nt = 0; nt < 8; nt++) {
        float bl = sb1[nt * 8 + tig * 2], bh = sb1[nt * 8 + tig * 2 + 1];
#pragma unroll
        for (int mt = 0; mt < 2; mt++) {
            d[mt][nt][0] = bl; d[mt][nt][1] = bh;
            d[mt][nt][2] = bl; d[mt][nt][3] = bh;
        }
    }
#pragma unroll
    for (int ks = 0; ks < 4; ks++) {
        uint32_t A[2][4];
#pragma unroll
        for (int mt = 0; mt < 2; mt++) {
            int r0 = mt * 16 + g, r1 = r0 + 8;
            int kc = ks * 16 + tig * 2;
            A[mt][0] = *reinterpret_cast<const uint32_t*>(&Xw[r0 * XPITCH + kc]);
            A[mt][1] = *reinterpret_cast<const uint32_t*>(&Xw[r1 * XPITCH + kc]);
            A[mt][2] = *reinterpret_cast<const uint32_t*>(&Xw[r0 * XPITCH + kc + 8]);
            A[mt][3] = *reinterpret_cast<const uint32_t*>(&Xw[r1 * XPITCH + kc + 8]);
        }
#pragma unroll
        for (int nt = 0; nt < 8; nt++) {
            const uint2 fb = __ldg(reinterpret_cast<const uint2*>(
                &g_bfrag[((nt * 4 + ks) * 32 + lane) * 2]));
            mma16816(d[0][nt][0], d[0][nt][1], d[0][nt][2], d[0][nt][3],
                     A[0][0], A[0][1], A[0][2], A[0][3], fb.x, fb.y);
            mma16816(d[1][nt][0], d[1][nt][1], d[1][nt][2], d[1][nt][3],
                     A[1][0], A[1][1], A[1][2], A[1][3], fb.x, fb.y);
        }
    }
    __syncwarp();
    // epilogue 1: h = tanh(D), write back over X tile
#pragma unroll
    for (int mt = 0; mt < 2; mt++) {
#pragma unroll
        for (int nt = 0; nt < 8; nt++) {
            int r0 = mt * 16 + g, r1 = r0 + 8;
            int c0 = nt * 8 + tig * 2;
            uint32_t h01 = cvt_bf2(tanh_hw(d[mt][nt][0]), tanh_hw(d[mt][nt][1]));
            uint32_t h23 = cvt_bf2(tanh_hw(d[mt][nt][2]), tanh_hw(d[mt][nt][3]));
            *reinterpret_cast<uint32_t*>(&Xw[r0 * XPITCH + c0]) = h01;
            *reinterpret_cast<uint32_t*>(&Xw[r1 * XPITCH + c0]) = h23;
        }
    }
    __syncwarp();

    // ---- Layer 2 ----
#pragma unroll
    for (int nt = 0; nt < 8; nt++) {
        float bl = sb2[nt * 8 + tig * 2], bh = sb2[nt * 8 + tig * 2 + 1];
#pragma unroll
        for (int mt = 0; mt < 2; mt++) {
            d[mt][nt][0] = bl; d[mt][nt][1] = bh;
            d[mt][nt][2] = bl; d[mt][nt][3] = bh;
        }
    }
#pragma unroll
    for (int ks = 0; ks < 4; ks++) {
        uint32_t A[2][4];
#pragma unroll
        for (int mt = 0; mt < 2; mt++) {
            int r0 = mt * 16 + g, r1 = r0 + 8;
            int kc = ks * 16 + tig * 2;
            A[mt][0] = *reinterpret_cast<const uint32_t*>(&Xw[r0 * XPITCH + kc]);
            A[mt][1] = *reinterpret_cast<const uint32_t*>(&Xw[r1 * XPITCH + kc]);
            A[mt][2] = *reinterpret_cast<const uint32_t*>(&Xw[r0 * XPITCH + kc + 8]);
            A[mt][3] = *reinterpret_cast<const uint32_t*>(&Xw[r1 * XPITCH + kc + 8]);
        }
#pragma unroll
        for (int nt = 0; nt < 8; nt++) {
            const uint2 fb = __ldg(reinterpret_cast<const uint2*>(
                &g_bfrag[(((8 + nt) * 4 + ks) * 32 + lane) * 2]));
            mma16816(d[0][nt][0], d[0][nt][1], d[0][nt][2], d[0][nt][3],
                     A[0][0], A[0][1], A[0][2], A[0][3], fb.x, fb.y);
            mma16816(d[1][nt][0], d[1][nt][1], d[1][nt][2], d[1][nt][3],
                     A[1][0], A[1][1], A[1][2], A[1][3], fb.x, fb.y);
        }
    }

    // ---- epilogue 2 + layer 3 + residual + store ----
#pragma unroll
    for (int mt = 0; mt < 2; mt++) {
        float s0[3] = {0.f, 0.f, 0.f};   // row mt*16+g
        float s1[3] = {0.f, 0.f, 0.f};   // row mt*16+g+8
#pragma unroll
        for (int nt = 0; nt < 8; nt++) {
            int c0 = nt * 8 + tig * 2, c1 = c0 + 1;
            float t00 = tanh_hw(d[mt][nt][0]);
            float t01 = tanh_hw(d[mt][nt][1]);
            float t10 = tanh_hw(d[mt][nt][2]);
            float t11 = tanh_hw(d[mt][nt][3]);
#pragma unroll
            for (int k = 0; k < 3; k++) {
                float w0 = sW3v[c0 * 3 + k], w1 = sW3v[c1 * 3 + k];
                s0[k] = fmaf(t00, w0, s0[k]); s0[k] = fmaf(t01, w1, s0[k]);
                s1[k] = fmaf(t10, w0, s1[k]); s1[k] = fmaf(t11, w1, s1[k]);
            }
        }
#pragma unroll
        for (int k = 0; k < 3; k++) {
            s0[k] += __shfl_xor_sync(0xffffffffu, s0[k], 1);
            s0[k] += __shfl_xor_sync(0xffffffffu, s0[k], 2);
            s1[k] += __shfl_xor_sync(0xffffffffu, s1[k], 1);
            s1[k] += __shfl_xor_sync(0xffffffffu, s1[k], 2);
        }
        if (tig == 0) {
            int p0 = pbase + mt * 16 + g;
            int p1 = p0 + 8;
#pragma unroll
            for (int k = 0; k < 3; k++) {
                float lo = __ldg(bbox + k), hi = __ldg(bbox + 3 + k);
                float scale = hi - lo;
                if (p0 < n) {
                    float xn = (__ldg(x + (size_t)p0 * 3 + k) - lo) / scale;
                    out[(size_t)p0 * 3 + k] = (s0[k] + sb3[k] + xn) * scale + lo;
                }
                if (p1 < n) {
                    float xn = (__ldg(x + (size_t)p1 * 3 + k) - lo) / scale;
                    out[(size_t)p1 * 3 + k] = (s1[k] + sb3[k] + xn) * scale + lo;
                }
            }
        }
    }
}

// ---------------------------------------------------------------------------
// kernel_launch: two launches, graph-capturable, allocation-free.
// Input order: x, e, tables, W1, b1, W2, b2, W3, b3, bounding_box
// ---------------------------------------------------------------------------
extern "C" void kernel_launch(void* const* d_in, const int* in_sizes, int n_in,
                              void* d_out, int out_size)
{
    const float* x      = (const float*)d_in[0];
    const float* e      = (const float*)d_in[1];
    const float* tables = (const float*)d_in[2];
    const float* W1     = (const float*)d_in[3];
    const float* b1     = (const float*)d_in[4];
    const float* W2     = (const float*)d_in[5];
    const float* b2     = (const float*)d_in[6];
    const float* W3     = (const float*)d_in[7];
    const float* b3     = (const float*)d_in[8];
    const float* bbox   = (const float*)d_in[9];

    int n = in_sizes[0] / 3;
    if (n > MAXN) n = MAXN;

    convert_weights<<<8, 256>>>(W1, W2);

    int blocks = (n + 127) / 128;
    fused_kernel<<<blocks, 128>>>(x, e, tables, b1, b2, W3, b3, bbox,
                                  (float*)d_out, n);
}

// round 14
// speedup vs baseline: 3.0322x; 1.4777x over previous
#include <cuda_runtime.h>
#include <cuda_bf16.h>
#include <cstdint>

#define NLEV   14
#define TMASK  524287u        // (1<<19)-1
#define PRIME1 2654435761u
#define PRIME2 805459861u
#define MAXN   500000
#define XPITCH 72             // smem row pitch in bf16 (144B -> conflict-free)
#define NBINS  262144         // 2^18 Morton bins (res-64 grid)

// ---- device scratch (bss, not allocations) ----
__device__ __align__(16) uint32_t g_bfrag[4096];  // mma B-fragments (2 layers)
__device__ uint32_t g_keys[MAXN];
__device__ int      g_order[MAXN];
__device__ int      g_hist[NBINS];
__device__ int      g_bsum[256];

__device__ __constant__ float c_res[NLEV] =
    {16.f, 21.f, 27.f, 36.f, 48.f, 64.f, 84.f, 111.f,
     147.f, 194.f, 256.f, 339.f, 447.f, 590.f};

// ---------------------------------------------------------------------------
// helpers (baseline PTX only — must assemble for plain sm_103)
// ---------------------------------------------------------------------------
__device__ __forceinline__ float tanh_hw(float x) {
    float y; asm("tanh.approx.f32 %0, %1;" : "=f"(y) : "f"(x)); return y;
}
__device__ __forceinline__ uint32_t cvt_bf2(float lo, float hi) {
    uint32_t r;
    asm("cvt.rn.bf16x2.f32 %0, %1, %2;" : "=r"(r) : "f"(hi), "f"(lo));
    return r;
}
__device__ __forceinline__ void mma16816(float& d0, float& d1, float& d2, float& d3,
                                         uint32_t a0, uint32_t a1, uint32_t a2, uint32_t a3,
                                         uint32_t b0, uint32_t b1) {
    asm volatile(
        "mma.sync.aligned.m16n8k16.row.col.f32.bf16.bf16.f32 "
        "{%0,%1,%2,%3}, {%4,%5,%6,%7}, {%8,%9}, {%0,%1,%2,%3};"
        : "+f"(d0), "+f"(d1), "+f"(d2), "+f"(d3)
        : "r"(a0), "r"(a1), "r"(a2), "r"(a3), "r"(b0), "r"(b1));
}
__device__ __forceinline__ uint32_t part1by2(uint32_t a) {
    a &= 0x3FFu;
    a = (a | (a << 16)) & 0x030000FFu;
    a = (a | (a << 8))  & 0x0300F00Fu;
    a = (a | (a << 4))  & 0x030C30C3u;
    a = (a | (a << 2))  & 0x09249249u;
    return a;
}

// ===========================================================================
// Kernel 0: pack W1 (zero-padded k>=36) and W2 into per-lane B-fragments
// ===========================================================================
__global__ void convert_weights(const float* __restrict__ W1,
                                const float* __restrict__ W2)
{
    int t = blockIdx.x * blockDim.x + threadIdx.x;
    if (t >= 2048) return;
    int lane = t & 31;
    int ks   = (t >> 5) & 3;
    int nt   = (t >> 7) & 7;
    int L    = (t >> 10);
    int g = lane >> 2, tig = lane & 3;
    int nn = nt * 8 + g;
    int k0 = ks * 16 + tig * 2;

    const float* Wm = L ? W2 : W1;
    float w00 = (L == 0 && k0     >= 36) ? 0.f : Wm[(k0)     * 64 + nn];
    float w01 = (L == 0 && k0 + 1 >= 36) ? 0.f : Wm[(k0 + 1) * 64 + nn];
    float w10 = (L == 0 && k0 + 8 >= 36) ? 0.f : Wm[(k0 + 8) * 64 + nn];
    float w11 = (L == 0 && k0 + 9 >= 36) ? 0.f : Wm[(k0 + 9) * 64 + nn];

    g_bfrag[t * 2 + 0] = cvt_bf2(w00, w01);
    g_bfrag[t * 2 + 1] = cvt_bf2(w10, w11);
}

// ===========================================================================
// Morton-bin counting sort (res-64 grid, 2^18 bins)
// ===========================================================================
__global__ void hist_zero() {
    int gid = blockIdx.x * 1024 + threadIdx.x;
    g_hist[gid] = 0;
}

__global__ void hist_build(const float* __restrict__ x,
                           const float* __restrict__ bbox, int n)
{
    int p = blockIdx.x * blockDim.x + threadIdx.x;
    if (p >= n) return;
    float lo0 = __ldg(bbox + 0), lo1 = __ldg(bbox + 1), lo2 = __ldg(bbox + 2);
    float hi0 = __ldg(bbox + 3), hi1 = __ldg(bbox + 4), hi2 = __ldg(bbox + 5);
    float xn0 = (__ldg(x + (size_t)p * 3 + 0) - lo0) / (hi0 - lo0);
    float xn1 = (__ldg(x + (size_t)p * 3 + 1) - lo1) / (hi1 - lo1);
    float xn2 = (__ldg(x + (size_t)p * 3 + 2) - lo2) / (hi2 - lo2);
    int c0 = min(max((int)(xn0 * 64.f), 0), 63);
    int c1 = min(max((int)(xn1 * 64.f), 0), 63);
    int c2 = min(max((int)(xn2 * 64.f), 0), 63);
    uint32_t key = (part1by2((uint32_t)c2) << 2) |
                   (part1by2((uint32_t)c1) << 1) |
                    part1by2((uint32_t)c0);
    g_keys[p] = key;
    atomicAdd(&g_hist[key], 1);
}

// exclusive scan of g_hist in 256 chunks of 1024
__global__ void scan_chunks() {
    __shared__ int buf[2][1024];
    int tid = threadIdx.x;
    int gid = blockIdx.x * 1024 + tid;
    int v = g_hist[gid];
    buf[0][tid] = v;
    __syncthreads();
    int src = 0;
#pragma unroll
    for (int off = 1; off < 1024; off <<= 1) {
        int t = buf[src][tid];
        if (tid >= off) t += buf[src][tid - off];
        buf[1 - src][tid] = t;
        src = 1 - src;
        __syncthreads();
    }
    int incl = buf[src][tid];
    g_hist[gid] = incl - v;                  // exclusive within chunk
    if (tid == 1023) g_bsum[blockIdx.x] = incl;
}

__global__ void scan_bsums() {
    __shared__ int buf[2][256];
    int tid = threadIdx.x;
    int v = g_bsum[tid];
    buf[0][tid] = v;
    __syncthreads();
    int src = 0;
#pragma unroll
    for (int off = 1; off < 256; off <<= 1) {
        int t = buf[src][tid];
        if (tid >= off) t += buf[src][tid - off];
        buf[1 - src][tid] = t;
        src = 1 - src;
        __syncthreads();
    }
    g_bsum[tid] = buf[src][tid] - v;         // exclusive
}

__global__ void scan_addback() {
    int gid = blockIdx.x * 1024 + threadIdx.x;
    g_hist[gid] += g_bsum[blockIdx.x];
}

__global__ void scatter_order(int n) {
    int p = blockIdx.x * blockDim.x + threadIdx.x;
    if (p >= n) return;
    uint32_t key = g_keys[p];
    int pos = atomicAdd(&g_hist[key], 1);
    g_order[pos] = p;
}

// ===========================================================================
// Fused kernel: encode (via Morton order) -> smem bf16 X-tile -> warp-MMA MLP
// ===========================================================================
__global__ void __launch_bounds__(128)
fused_kernel(const float* __restrict__ x,
             const float* __restrict__ e,
             const float* __restrict__ tables,
             const float* __restrict__ b1, const float* __restrict__ b2,
             const float* __restrict__ W3, const float* __restrict__ b3,
             const float* __restrict__ bbox,
             float* __restrict__ out,
             int n)
{
    __shared__ __align__(16) __nv_bfloat16 sX[128 * XPITCH];   // 18.4 KB
    __shared__ float sb1[64], sb2[64], sW3v[192], sb3[3];
    __shared__ float sXn[128 * 3];
    __shared__ int   sPid[128];

    const int tid  = threadIdx.x;
    const int w    = tid >> 5;
    const int lane = tid & 31;
    const int g    = lane >> 2;
    const int tig  = lane & 3;

    if (tid < 64) { sb1[tid] = b1[tid]; sb2[tid] = b2[tid]; }
    if (tid < 96) { sW3v[tid] = W3[tid]; sW3v[96 + tid] = W3[96 + tid]; }
    if (tid < 3)  sb3[tid] = b3[tid];

    // ================= encode phase (this thread's point via order) =======
    const int i  = blockIdx.x * 128 + tid;
    const bool valid = (i < n);
    const int p  = valid ? g_order[i] : g_order[0];
    sPid[tid] = valid ? p : -1;

    float lo0 = __ldg(bbox + 0), lo1 = __ldg(bbox + 1), lo2 = __ldg(bbox + 2);
    float hi0 = __ldg(bbox + 3), hi1 = __ldg(bbox + 4), hi2 = __ldg(bbox + 5);

    float xv0 = __ldg(x + (size_t)p * 3 + 0);
    float xv1 = __ldg(x + (size_t)p * 3 + 1);
    float xv2 = __ldg(x + (size_t)p * 3 + 2);

    float xn0 = (xv0 - lo0) / (hi0 - lo0);
    float xn1 = (xv1 - lo1) / (hi1 - lo1);
    float xn2 = (xv2 - lo2) / (hi2 - lo2);

    sXn[tid * 3 + 0] = xn0;
    sXn[tid * 3 + 1] = xn1;
    sXn[tid * 3 + 2] = xn2;

    float f[2 * NLEV];

#pragma unroll
    for (int l = 0; l < NLEV; l++) {
        float r  = c_res[l];
        float p0 = xn0 * r, p1v = xn1 * r, p2v = xn2 * r;
        float b0 = floorf(p0), b1f = floorf(p1v), b2f = floorf(p2v);
        float fr0 = p0 - b0, fr1 = p1v - b1f, fr2 = p2v - b2f;

        float w0 = fr0 * fr0 * (3.0f - 2.0f * fr0);
        float w1 = fr1 * fr1 * (3.0f - 2.0f * fr1);
        float w2 = fr2 * fr2 * (3.0f - 2.0f * fr2);
        float u0 = 1.0f - w0, u1 = 1.0f - w1, u2 = 1.0f - w2;

        unsigned c0 = (unsigned)b0, c1 = (unsigned)b1f, c2 = (unsigned)b2f;
        unsigned hx0 = c0,            hx1 = c0 + 1u;
        unsigned hy0 = c1 * PRIME1,   hy1 = hy0 + PRIME1;
        unsigned hz0 = c2 * PRIME2,   hz1 = hz0 + PRIME2;

        const float2* tl = reinterpret_cast<const float2*>(tables) + ((size_t)l << 19);

        unsigned i000 = (hx0 ^ hy0 ^ hz0) & TMASK;
        unsigned i001 = (hx0 ^ hy0 ^ hz1) & TMASK;
        unsigned i010 = (hx0 ^ hy1 ^ hz0) & TMASK;
        unsigned i011 = (hx0 ^ hy1 ^ hz1) & TMASK;
        unsigned i100 = (hx1 ^ hy0 ^ hz0) & TMASK;
        unsigned i101 = (hx1 ^ hy0 ^ hz1) & TMASK;
        unsigned i110 = (hx1 ^ hy1 ^ hz0) & TMASK;
        unsigned i111 = (hx1 ^ hy1 ^ hz1) & TMASK;

        float2 t000 = __ldg(tl + i000);
        float2 t001 = __ldg(tl + i001);
        float2 t010 = __ldg(tl + i010);
        float2 t011 = __ldg(tl + i011);
        float2 t100 = __ldg(tl + i100);
        float2 t101 = __ldg(tl + i101);
        float2 t110 = __ldg(tl + i110);
        float2 t111 = __ldg(tl + i111);

        float w00 = u0 * u1, w01 = u0 * w1, w10 = w0 * u1, w11 = w0 * w1;
        float w000 = w00 * u2, w001 = w00 * w2;
        float w010 = w01 * u2, w011 = w01 * w2;
        float w100 = w10 * u2, w101 = w10 * w2;
        float w110 = w11 * u2, w111 = w11 * w2;

        float a0 = w000 * t000.x; float a1 = w000 * t000.y;
        a0 = fmaf(w001, t001.x, a0); a1 = fmaf(w001, t001.y, a1);
        a0 = fmaf(w010, t010.x, a0); a1 = fmaf(w010, t010.y, a1);
        a0 = fmaf(w011, t011.x, a0); a1 = fmaf(w011, t011.y, a1);
        a0 = fmaf(w100, t100.x, a0); a1 = fmaf(w100, t100.y, a1);
        a0 = fmaf(w101, t101.x, a0); a1 = fmaf(w101, t101.y, a1);
        a0 = fmaf(w110, t110.x, a0); a1 = fmaf(w110, t110.y, a1);
        a0 = fmaf(w111, t111.x, a0); a1 = fmaf(w111, t111.y, a1);

        f[2 * l]     = a0;
        f[2 * l + 1] = a1;
    }

    // pack row into this thread's smem X row
    {
        uint32_t pk[32];
#pragma unroll
        for (int q = 0; q < 14; q++) pk[q] = cvt_bf2(f[2 * q], f[2 * q + 1]);
        const float4* ep = reinterpret_cast<const float4*>(e + (size_t)p * 8);
        float4 v0 = ep[0], v1 = ep[1];
        pk[14] = cvt_bf2(v0.x, v0.y);
        pk[15] = cvt_bf2(v0.z, v0.w);
        pk[16] = cvt_bf2(v1.x, v1.y);
        pk[17] = cvt_bf2(v1.z, v1.w);
#pragma unroll
        for (int q = 18; q < 32; q++) pk[q] = 0u;

        __nv_bfloat16* dst = &sX[tid * XPITCH];
#pragma unroll
        for (int c = 0; c < 8; c++)
            *reinterpret_cast<uint4*>(dst + c * 8) =
                make_uint4(pk[4 * c], pk[4 * c + 1], pk[4 * c + 2], pk[4 * c + 3]);
    }
    __syncthreads();

    // ================= MMA MLP phase =================
    __nv_bfloat16* Xw = &sX[w * 32 * XPITCH];
    float d[2][8][4];

    // ---- Layer 1 ----
#pragma unroll
    for (int nt = 0; nt < 8; nt++) {
        float bl = sb1[nt * 8 + tig * 2], bh = sb1[nt * 8 + tig * 2 + 1];
#pragma unroll
        for (int mt = 0; mt < 2; mt++) {
            d[mt][nt][0] = bl; d[mt][nt][1] = bh;
            d[mt][nt][2] = bl; d[mt][nt][3] = bh;
        }
    }
#pragma unroll
    for (int ks = 0; ks < 4; ks++) {
        uint32_t A[2][4];
#pragma unroll
        for (int mt = 0; mt < 2; mt++) {
            int r0 = mt * 16 + g, r1 = r0 + 8;
            int kc = ks * 16 + tig * 2;
            A[mt][0] = *reinterpret_cast<const uint32_t*>(&Xw[r0 * XPITCH + kc]);
            A[mt][1] = *reinterpret_cast<const uint32_t*>(&Xw[r1 * XPITCH + kc]);
            A[mt][2] = *reinterpret_cast<const uint32_t*>(&Xw[r0 * XPITCH + kc + 8]);
            A[mt][3] = *reinterpret_cast<const uint32_t*>(&Xw[r1 * XPITCH + kc + 8]);
        }
#pragma unroll
        for (int nt = 0; nt < 8; nt++) {
            const uint2 fb = __ldg(reinterpret_cast<const uint2*>(
                &g_bfrag[((nt * 4 + ks) * 32 + lane) * 2]));
            mma16816(d[0][nt][0], d[0][nt][1], d[0][nt][2], d[0][nt][3],
                     A[0][0], A[0][1], A[0][2], A[0][3], fb.x, fb.y);
            mma16816(d[1][nt][0], d[1][nt][1], d[1][nt][2], d[1][nt][3],
                     A[1][0], A[1][1], A[1][2], A[1][3], fb.x, fb.y);
        }
    }
    __syncwarp();
#pragma unroll
    for (int mt = 0; mt < 2; mt++) {
#pragma unroll
        for (int nt = 0; nt < 8; nt++) {
            int r0 = mt * 16 + g, r1 = r0 + 8;
            int c0 = nt * 8 + tig * 2;
            uint32_t h01 = cvt_bf2(tanh_hw(d[mt][nt][0]), tanh_hw(d[mt][nt][1]));
            uint32_t h23 = cvt_bf2(tanh_hw(d[mt][nt][2]), tanh_hw(d[mt][nt][3]));
            *reinterpret_cast<uint32_t*>(&Xw[r0 * XPITCH + c0]) = h01;
            *reinterpret_cast<uint32_t*>(&Xw[r1 * XPITCH + c0]) = h23;
        }
    }
    __syncwarp();

    // ---- Layer 2 ----
#pragma unroll
    for (int nt = 0; nt < 8; nt++) {
        float bl = sb2[nt * 8 + tig * 2], bh = sb2[nt * 8 + tig * 2 + 1];
#pragma unroll
        for (int mt = 0; mt < 2; mt++) {
            d[mt][nt][0] = bl; d[mt][nt][1] = bh;
            d[mt][nt][2] = bl; d[mt][nt][3] = bh;
        }
    }
#pragma unroll
    for (int ks = 0; ks < 4; ks++) {
        uint32_t A[2][4];
#pragma unroll
        for (int mt = 0; mt < 2; mt++) {
            int r0 = mt * 16 + g, r1 = r0 + 8;
            int kc = ks * 16 + tig * 2;
            A[mt][0] = *reinterpret_cast<const uint32_t*>(&Xw[r0 * XPITCH + kc]);
            A[mt][1] = *reinterpret_cast<const uint32_t*>(&Xw[r1 * XPITCH + kc]);
            A[mt][2] = *reinterpret_cast<const uint32_t*>(&Xw[r0 * XPITCH + kc + 8]);
            A[mt][3] = *reinterpret_cast<const uint32_t*>(&Xw[r1 * XPITCH + kc + 8]);
        }
#pragma unroll
        for (int nt = 0; nt < 8; nt++) {
            const uint2 fb = __ldg(reinterpret_cast<const uint2*>(
                &g_bfrag[(((8 + nt) * 4 + ks) * 32 + lane) * 2]));
            mma16816(d[0][nt][0], d[0][nt][1], d[0][nt][2], d[0][nt][3],
                     A[0][0], A[0][1], A[0][2], A[0][3], fb.x, fb.y);
            mma16816(d[1][nt][0], d[1][nt][1], d[1][nt][2], d[1][nt][3],
                     A[1][0], A[1][1], A[1][2], A[1][3], fb.x, fb.y);
        }
    }

    // ---- epilogue 2 + layer 3 + residual + scatter store ----
#pragma unroll
    for (int mt = 0; mt < 2; mt++) {
        float s0[3] = {0.f, 0.f, 0.f};
        float s1[3] = {0.f, 0.f, 0.f};
#pragma unroll
        for (int nt = 0; nt < 8; nt++) {
            int c0 = nt * 8 + tig * 2, c1 = c0 + 1;
            float t00 = tanh_hw(d[mt][nt][0]);
            float t01 = tanh_hw(d[mt][nt][1]);
            float t10 = tanh_hw(d[mt][nt][2]);
            float t11 = tanh_hw(d[mt][nt][3]);
#pragma unroll
            for (int k = 0; k < 3; k++) {
                float w0 = sW3v[c0 * 3 + k], w1 = sW3v[c1 * 3 + k];
                s0[k] = fmaf(t00, w0, s0[k]); s0[k] = fmaf(t01, w1, s0[k]);
                s1[k] = fmaf(t10, w0, s1[k]); s1[k] = fmaf(t11, w1, s1[k]);
            }
        }
#pragma unroll
        for (int k = 0; k < 3; k++) {
            s0[k] += __shfl_xor_sync(0xffffffffu, s0[k], 1);
            s0[k] += __shfl_xor_sync(0xffffffffu, s0[k], 2);
            s1[k] += __shfl_xor_sync(0xffffffffu, s1[k], 1);
            s1[k] += __shfl_xor_sync(0xffffffffu, s1[k], 2);
        }
        if (tig == 0) {
            int row0 = w * 32 + mt * 16 + g;
            int row1 = row0 + 8;
            int pid0 = sPid[row0];
            int pid1 = sPid[row1];
#pragma unroll
            for (int k = 0; k < 3; k++) {
                float lo = __ldg(bbox + k), hi = __ldg(bbox + 3 + k);
                float scale = hi - lo;
                if (pid0 >= 0) {
                    float xn = sXn[row0 * 3 + k];
                    out[(size_t)pid0 * 3 + k] = (s0[k] + sb3[k] + xn) * scale + lo;
                }
                if (pid1 >= 0) {
                    float xn = sXn[row1 * 3 + k];
                    out[(size_t)pid1 * 3 + k] = (s1[k] + sb3[k] + xn) * scale + lo;
                }
            }
        }
    }
}

// ---------------------------------------------------------------------------
// kernel_launch: weight pack + Morton counting sort + fused kernel.
// All plain kernel launches -> graph-capturable, allocation-free.
// Input order: x, e, tables, W1, b1, W2, b2, W3, b3, bounding_box
// ---------------------------------------------------------------------------
extern "C" void kernel_launch(void* const* d_in, const int* in_sizes, int n_in,
                              void* d_out, int out_size)
{
    const float* x      = (const float*)d_in[0];
    const float* e      = (const float*)d_in[1];
    const float* tables = (const float*)d_in[2];
    const float* W1     = (const float*)d_in[3];
    const float* b1     = (const float*)d_in[4];
    const float* W2     = (const float*)d_in[5];
    const float* b2     = (const float*)d_in[6];
    const float* W3     = (const float*)d_in[7];
    const float* b3     = (const float*)d_in[8];
    const float* bbox   = (const float*)d_in[9];

    int n = in_sizes[0] / 3;
    if (n > MAXN) n = MAXN;

    convert_weights<<<8, 256>>>(W1, W2);

    // Morton-bin counting sort
    hist_zero<<<NBINS / 1024, 1024>>>();
    hist_build<<<(n + 255) / 256, 256>>>(x, bbox, n);
    scan_chunks<<<256, 1024>>>();
    scan_bsums<<<1, 256>>>();
    scan_addback<<<256, 1024>>>();
    scatter_order<<<(n + 255) / 256, 256>>>(n);

    int blocks = (n + 127) / 128;
    fused_kernel<<<blocks, 128>>>(x, e, tables, b1, b2, W3, b3, bbox,
                                  (float*)d_out, n);
}